// round 3
// baseline (speedup 1.0000x reference)
#include <cuda_runtime.h>
#include <math.h>

// ---------------- problem constants ----------------
#define NB   16
#define NT   512
#define TOK  (NB*NT)        // 8192 tokens
#define HD   768
#define T3   (3*HD)         // 2304
#define DFF  3072
#define NHH  12
#define DH   64
#define NLB  9
#define NBH  (NB*NHH)       // 192
#define NLAY 4

// ---------------- scratch (static device globals; no runtime alloc) ----------------
__device__ float g_x[TOK*HD];
__device__ float g_qkv[TOK*T3];
__device__ float g_scores[(size_t)NBH*NT*NT];   // 201 MB
__device__ float g_ctx[TOK*HD];
__device__ float g_y[TOK*HD];
__device__ float g_ff[TOK*DFF];
__device__ float g_logits[TOK*NLB];
__device__ float g_llh[NB];

// ---------------- reductions ----------------
__device__ __forceinline__ void reduce2_256(float& a, float& b) {
    __shared__ float sa[8], sb[8];
    #pragma unroll
    for (int o = 16; o; o >>= 1) {
        a += __shfl_xor_sync(0xffffffffu, a, o);
        b += __shfl_xor_sync(0xffffffffu, b, o);
    }
    int w = threadIdx.x >> 5;
    if ((threadIdx.x & 31) == 0) { sa[w] = a; sb[w] = b; }
    __syncthreads();
    a = 0.f; b = 0.f;
    #pragma unroll
    for (int i = 0; i < 8; i++) { a += sa[i]; b += sb[i]; }
}

// ---------------- embedding + LN ----------------
__global__ void __launch_bounds__(256) embed_ln_kernel(
    const int* __restrict__ ids, const int* __restrict__ tt,
    const float* __restrict__ we, const float* __restrict__ pe, const float* __restrict__ te,
    const float* __restrict__ sc, const float* __restrict__ bi, float* __restrict__ x)
{
    int tok = blockIdx.x;
    int t   = tok & (NT - 1);
    int tid = threadIdx.x;
    const float* w  = we + (size_t)ids[tok] * HD;
    const float* p  = pe + (size_t)t * HD;
    const float* ty = te + (size_t)tt[tok] * HD;
    float e[3]; float sum = 0.f, sq = 0.f;
    #pragma unroll
    for (int i = 0; i < 3; i++) {
        int c = tid + i * 256;
        float v = w[c] + p[c] + ty[c];
        e[i] = v; sum += v; sq += v * v;
    }
    reduce2_256(sum, sq);
    float mean = sum * (1.f / HD);
    float var  = sq * (1.f / HD) - mean * mean;
    float inv  = rsqrtf(var + 1e-12f);
    #pragma unroll
    for (int i = 0; i < 3; i++) {
        int c = tid + i * 256;
        x[(size_t)tok * HD + c] = (e[i] - mean) * inv * sc[c] + bi[c];
    }
}

// ---------------- residual + LN (in-place on x) ----------------
__global__ void __launch_bounds__(256) ln_res_kernel(
    const float* __restrict__ xin, const float* __restrict__ y,
    const float* __restrict__ sc, const float* __restrict__ bi, float* __restrict__ xout)
{
    int tok = blockIdx.x;
    int tid = threadIdx.x;
    float e[3]; float sum = 0.f, sq = 0.f;
    #pragma unroll
    for (int i = 0; i < 3; i++) {
        int c = tid + i * 256;
        float v = xin[(size_t)tok * HD + c] + y[(size_t)tok * HD + c];
        e[i] = v; sum += v; sq += v * v;
    }
    reduce2_256(sum, sq);
    float mean = sum * (1.f / HD);
    float var  = sq * (1.f / HD) - mean * mean;
    float inv  = rsqrtf(var + 1e-12f);
    #pragma unroll
    for (int i = 0; i < 3; i++) {
        int c = tid + i * 256;
        xout[(size_t)tok * HD + c] = (e[i] - mean) * inv * sc[c] + bi[c];
    }
}

// ---------------- SGEMM: C[M,N] = A[M,K] @ B[K,N] + bias; EPI=1 -> tanh-GELU ----------------
// M % 128 == 0, N % 128 == 0, K % 8 == 0 (holds for all call sites).
template<int EPI>
__global__ void __launch_bounds__(256) gemm_bias(
    const float* __restrict__ A, const float* __restrict__ B,
    const float* __restrict__ bias, float* __restrict__ C,
    int M, int N, int K)
{
    __shared__ float As[8][128];
    __shared__ float Bs[8][128];
    int tid = threadIdx.x;
    int m0 = blockIdx.y * 128;
    int n0 = blockIdx.x * 128;
    int tx = tid & 15, ty = tid >> 4;

    int arow = tid >> 1;
    int acol = (tid & 1) * 4;
    int brow = tid >> 5;
    int bcol = (tid & 31) * 4;
    const float* Aptr = A + (size_t)(m0 + arow) * K + acol;
    const float* Bptr = B + (size_t)brow * N + n0 + bcol;

    float c[8][8] = {};
    for (int k0 = 0; k0 < K; k0 += 8) {
        float4 av = *(const float4*)(Aptr + k0);
        float4 bv = *(const float4*)(Bptr + (size_t)k0 * N);
        As[acol + 0][arow] = av.x;
        As[acol + 1][arow] = av.y;
        As[acol + 2][arow] = av.z;
        As[acol + 3][arow] = av.w;
        *(float4*)&Bs[brow][bcol] = bv;
        __syncthreads();
        #pragma unroll
        for (int kk = 0; kk < 8; kk++) {
            float a[8], b[8];
            *(float4*)(a)     = *(const float4*)&As[kk][ty * 8];
            *(float4*)(a + 4) = *(const float4*)&As[kk][ty * 8 + 4];
            *(float4*)(b)     = *(const float4*)&Bs[kk][tx * 8];
            *(float4*)(b + 4) = *(const float4*)&Bs[kk][tx * 8 + 4];
            #pragma unroll
            for (int i = 0; i < 8; i++)
                #pragma unroll
                for (int j = 0; j < 8; j++)
                    c[i][j] = fmaf(a[i], b[j], c[i][j]);
        }
        __syncthreads();
    }
    #pragma unroll
    for (int i = 0; i < 8; i++) {
        size_t m = m0 + ty * 8 + i;
        #pragma unroll
        for (int j = 0; j < 8; j++) {
            int n = n0 + tx * 8 + j;
            float v = c[i][j] + bias[n];
            if (EPI == 1) {
                float u = 0.7978845608028654f * (v + 0.044715f * v * v * v);
                v = 0.5f * v * (1.f + tanhf(u));
            }
            C[m * N + n] = v;
        }
    }
}

// ---------------- attention: S = Q @ K^T (raw dot, scale applied in softmax) ----------------
__global__ void __launch_bounds__(256) qk_kernel(
    const float* __restrict__ qkv, float* __restrict__ scores)
{
    __shared__ float Qs[64][65];
    __shared__ float Ks[64][65];
    int bh = blockIdx.z;
    int b = bh / NHH, h = bh % NHH;
    int m0 = blockIdx.y * 64, n0 = blockIdx.x * 64;
    const float* Q  = qkv + (size_t)(b * NT + m0) * T3 + h * DH;
    const float* Kp = qkv + (size_t)(b * NT + n0) * T3 + HD + h * DH;
    int tid = threadIdx.x;
    #pragma unroll
    for (int cc = 0; cc < 4; cc++) {
        int idx = cc * 1024 + tid * 4;
        int r = idx >> 6, col = idx & 63;
        float4 qv = *(const float4*)(Q  + (size_t)r * T3 + col);
        Qs[col + 0][r] = qv.x; Qs[col + 1][r] = qv.y; Qs[col + 2][r] = qv.z; Qs[col + 3][r] = qv.w;
        float4 kv = *(const float4*)(Kp + (size_t)r * T3 + col);
        Ks[col + 0][r] = kv.x; Ks[col + 1][r] = kv.y; Ks[col + 2][r] = kv.z; Ks[col + 3][r] = kv.w;
    }
    __syncthreads();
    int tx = tid & 15, ty = tid >> 4;
    float acc[4][4] = {};
    #pragma unroll 8
    for (int k = 0; k < 64; k++) {
        float a[4], bv[4];
        #pragma unroll
        for (int i = 0; i < 4; i++) a[i]  = Qs[k][ty * 4 + i];
        #pragma unroll
        for (int j = 0; j < 4; j++) bv[j] = Ks[k][tx * 4 + j];
        #pragma unroll
        for (int i = 0; i < 4; i++)
            #pragma unroll
            for (int j = 0; j < 4; j++)
                acc[i][j] = fmaf(a[i], bv[j], acc[i][j]);
    }
    float* out = scores + (size_t)bh * NT * NT;
    #pragma unroll
    for (int i = 0; i < 4; i++)
        #pragma unroll
        for (int j = 0; j < 4; j++)
            out[(size_t)(m0 + ty * 4 + i) * NT + n0 + tx * 4 + j] = acc[i][j];
}

// ---------------- softmax over key dim, with additive mask, scale=1/8 ----------------
__global__ void __launch_bounds__(128) softmax_kernel(
    float* __restrict__ scores, const int* __restrict__ amask)
{
    __shared__ float sm[4];
    int row = blockIdx.x;           // bh*512 + q
    int bh  = row >> 9;
    int b   = bh / NHH;
    float* p = scores + (size_t)row * NT;
    int tid = threadIdx.x;
    float v[4]; float mx = -1e30f;
    #pragma unroll
    for (int c = 0; c < 4; c++) {
        int col = tid + c * 128;
        float madd = (1.f - (float)amask[b * NT + col]) * -1e9f;
        v[c] = p[col] * 0.125f + madd;
        mx = fmaxf(mx, v[c]);
    }
    #pragma unroll
    for (int o = 16; o; o >>= 1) mx = fmaxf(mx, __shfl_xor_sync(0xffffffffu, mx, o));
    if ((tid & 31) == 0) sm[tid >> 5] = mx;
    __syncthreads();
    mx = fmaxf(fmaxf(sm[0], sm[1]), fmaxf(sm[2], sm[3]));
    __syncthreads();
    float sum = 0.f;
    #pragma unroll
    for (int c = 0; c < 4; c++) { v[c] = __expf(v[c] - mx); sum += v[c]; }
    #pragma unroll
    for (int o = 16; o; o >>= 1) sum += __shfl_xor_sync(0xffffffffu, sum, o);
    if ((tid & 31) == 0) sm[tid >> 5] = sum;
    __syncthreads();
    sum = sm[0] + sm[1] + sm[2] + sm[3];
    float inv = 1.f / sum;
    #pragma unroll
    for (int c = 0; c < 4; c++) p[tid + c * 128] = v[c] * inv;
}

// ---------------- ctx = S @ V ----------------
__global__ void __launch_bounds__(256) av_kernel(
    const float* __restrict__ scores, const float* __restrict__ qkv, float* __restrict__ ctx)
{
    __shared__ float Ss[32][65];
    __shared__ float Vs[32][68];
    int bh = blockIdx.y;
    int b = bh / NHH, h = bh % NHH;
    int m0 = blockIdx.x * 64;
    const float* S = scores + (size_t)bh * NT * NT + (size_t)m0 * NT;
    const float* V = qkv + (size_t)(b * NT) * T3 + 2 * HD + h * DH;
    int tid = threadIdx.x;
    int tx = tid & 15, ty = tid >> 4;
    float acc[4][4] = {};
    for (int kb = 0; kb < NT; kb += 32) {
        #pragma unroll
        for (int cc = 0; cc < 2; cc++) {
            int idx = cc * 1024 + tid * 4;
            int r = idx >> 5, k = idx & 31;
            float4 sv = *(const float4*)(S + (size_t)r * NT + kb + k);
            Ss[k + 0][r] = sv.x; Ss[k + 1][r] = sv.y; Ss[k + 2][r] = sv.z; Ss[k + 3][r] = sv.w;
            int vr = idx >> 6, vc = idx & 63;
            float4 vv = *(const float4*)(V + (size_t)(kb + vr) * T3 + vc);
            *(float4*)&Vs[vr][vc] = vv;
        }
        __syncthreads();
        #pragma unroll 8
        for (int k = 0; k < 32; k++) {
            float a[4], bv[4];
            #pragma unroll
            for (int i = 0; i < 4; i++) a[i]  = Ss[k][ty * 4 + i];
            #pragma unroll
            for (int j = 0; j < 4; j++) bv[j] = Vs[k][tx * 4 + j];
            #pragma unroll
            for (int i = 0; i < 4; i++)
                #pragma unroll
                for (int j = 0; j < 4; j++)
                    acc[i][j] = fmaf(a[i], bv[j], acc[i][j]);
        }
        __syncthreads();
    }
    #pragma unroll
    for (int i = 0; i < 4; i++)
        #pragma unroll
        for (int j = 0; j < 4; j++)
            ctx[(size_t)(b * NT + m0 + ty * 4 + i) * HD + h * DH + tx * 4 + j] = acc[i][j];
}

// ---------------- classifier: logits = x @ Wcls + bcls ----------------
__global__ void __launch_bounds__(256) cls_kernel(
    const float* __restrict__ x, const float* __restrict__ W,
    const float* __restrict__ bias, float* __restrict__ out)
{
    int idx = blockIdx.x * blockDim.x + threadIdx.x;
    if (idx >= TOK * NLB) return;
    int tok = idx / NLB, n = idx % NLB;
    const float* xr = x + (size_t)tok * HD;
    float s = bias[n];
    #pragma unroll 8
    for (int k = 0; k < HD; k++) s = fmaf(xr[k], W[k * NLB + n], s);
    out[idx] = s;
}

// ---------------- CRF: forward (logZ), numerator, Viterbi + backtrack ----------------
__global__ void __launch_bounds__(128) crf_kernel(
    const float* __restrict__ logits, const int* __restrict__ labels,
    const int* __restrict__ amask, const float* __restrict__ startv,
    const float* __restrict__ endv, const float* __restrict__ trans,
    float* __restrict__ llh, float* __restrict__ dout)
{
    __shared__ float em[511 * NLB];
    __shared__ float tr[NLB * NLB];
    __shared__ unsigned char bp[510 * NLB];
    __shared__ float mk[511];
    __shared__ int   tg[511];
    __shared__ float sd[NLB], sv[NLB];

    int b = blockIdx.x, tid = threadIdx.x;
    const float* lp = logits + (size_t)(b * NT + 1) * NLB;   // skip [CLS]
    for (int i = tid; i < 511 * NLB; i += blockDim.x) em[i] = lp[i];
    for (int i = tid; i < NLB * NLB; i += blockDim.x) tr[i] = trans[i];
    for (int i = tid; i < 511; i += blockDim.x) {
        mk[i] = (float)amask[b * NT + 1 + i];
        tg[i] = labels[b * NT + 1 + i];
    }
    __syncthreads();

    if (tid < 32) {
        int j = tid;
        float tc[NLB];
        if (j < NLB) {
            #pragma unroll
            for (int i = 0; i < NLB; i++) tc[i] = tr[i * NLB + j];
            sd[j] = startv[j] + em[j];
            sv[j] = sd[j];
        }
        __syncwarp();
        float num = 0.f; int prev = 0;
        if (j == 0) { prev = tg[0]; num = startv[prev] + em[prev]; }

        for (int s = 1; s < 511; s++) {
            float m = mk[s];
            float nd = 0.f, nv = 0.f; int bi = 0;
            if (j < NLB) {
                float e = em[s * NLB + j];
                float mx = -1e30f;
                #pragma unroll
                for (int i = 0; i < NLB; i++) { float v = sd[i] + tc[i]; mx = fmaxf(mx, v); }
                float sum = 0.f;
                #pragma unroll
                for (int i = 0; i < NLB; i++) sum += __expf(sd[i] + tc[i] - mx);
                nd = mx + __logf(sum) + e;
                float bv = -1e30f;
                #pragma unroll
                for (int i = 0; i < NLB; i++) {
                    float v = sv[i] + tc[i];
                    if (v > bv) { bv = v; bi = i; }
                }
                bp[(s - 1) * NLB + j] = (unsigned char)bi;
                nv = bv + e;
            }
            __syncwarp();
            if (j < NLB && m > 0.f) { sd[j] = nd; sv[j] = nv; }
            if (j == 0) {
                int t = tg[s];
                num += m * (tr[prev * NLB + t] + em[s * NLB + t]);
                if (m > 0.f) prev = t;
            }
            __syncwarp();
        }

        if (j == 0) {
            num += endv[prev];
            float mx = -1e30f;
            #pragma unroll
            for (int i = 0; i < NLB; i++) mx = fmaxf(mx, sd[i] + endv[i]);
            float sum = 0.f;
            #pragma unroll
            for (int i = 0; i < NLB; i++) sum += __expf(sd[i] + endv[i] - mx);
            float den = mx + __logf(sum);
            llh[b] = num - den;

            float bv = -1e30f; int last = 0;
            #pragma unroll
            for (int i = 0; i < NLB; i++) {
                float v = sv[i] + endv[i];
                if (v > bv) { bv = v; last = i; }
            }
            float* pd = dout + 1 + (size_t)b * 511;
            pd[510] = (float)last;
            for (int s = 509; s >= 0; s--) {
                last = bp[s * NLB + last];
                pd[s] = (float)last;
            }
        }
    }
}

__global__ void loss_kernel(const float* __restrict__ llh, float* __restrict__ dout)
{
    if (threadIdx.x == 0) {
        float s = 0.f;
        for (int i = 0; i < NB; i++) s += llh[i];
        dout[0] = -s / (float)NB;
    }
}

// ---------------- launcher ----------------
extern "C" void kernel_launch(void* const* d_in, const int* in_sizes, int n_in,
                              void* d_out, int out_size)
{
    (void)in_sizes; (void)n_in; (void)out_size;
    const int*   ids  = (const int*)d_in[0];
    const int*   am   = (const int*)d_in[1];
    const int*   tti  = (const int*)d_in[2];
    const int*   lab  = (const int*)d_in[3];
    const float* we   = (const float*)d_in[4];
    const float* pe   = (const float*)d_in[5];
    const float* te   = (const float*)d_in[6];
    const float* elns = (const float*)d_in[7];
    const float* elnb = (const float*)d_in[8];
    const float* Wqkv = (const float*)d_in[9];
    const float* bqkv = (const float*)d_in[10];
    const float* Wo   = (const float*)d_in[11];
    const float* bo   = (const float*)d_in[12];
    const float* l1s  = (const float*)d_in[13];
    const float* l1b  = (const float*)d_in[14];
    const float* W1   = (const float*)d_in[15];
    const float* b1   = (const float*)d_in[16];
    const float* W2   = (const float*)d_in[17];
    const float* b2   = (const float*)d_in[18];
    const float* l2s  = (const float*)d_in[19];
    const float* l2b  = (const float*)d_in[20];
    const float* Wcls = (const float*)d_in[21];
    const float* bcls = (const float*)d_in[22];
    const float* cst  = (const float*)d_in[23];
    const float* cen  = (const float*)d_in[24];
    const float* ctr  = (const float*)d_in[25];
    float* out = (float*)d_out;

    float *x, *qkv, *sc, *ctx, *y, *ff, *lg, *llh;
    cudaGetSymbolAddress((void**)&x,   g_x);
    cudaGetSymbolAddress((void**)&qkv, g_qkv);
    cudaGetSymbolAddress((void**)&sc,  g_scores);
    cudaGetSymbolAddress((void**)&ctx, g_ctx);
    cudaGetSymbolAddress((void**)&y,   g_y);
    cudaGetSymbolAddress((void**)&ff,  g_ff);
    cudaGetSymbolAddress((void**)&lg,  g_logits);
    cudaGetSymbolAddress((void**)&llh, g_llh);

    embed_ln_kernel<<<TOK, 256>>>(ids, tti, we, pe, te, elns, elnb, x);

    for (int l = 0; l < NLAY; l++) {
        gemm_bias<0><<<dim3(T3 / 128, TOK / 128), 256>>>(
            x, Wqkv + (size_t)l * HD * T3, bqkv + (size_t)l * T3, qkv, TOK, T3, HD);
        qk_kernel<<<dim3(8, 8, NBH), 256>>>(qkv, sc);
        softmax_kernel<<<NBH * NT, 128>>>(sc, am);
        av_kernel<<<dim3(8, NBH), 256>>>(sc, qkv, ctx);
        gemm_bias<0><<<dim3(HD / 128, TOK / 128), 256>>>(
            ctx, Wo + (size_t)l * HD * HD, bo + (size_t)l * HD, y, TOK, HD, HD);
        ln_res_kernel<<<TOK, 256>>>(x, y, l1s + (size_t)l * HD, l1b + (size_t)l * HD, x);
        gemm_bias<1><<<dim3(DFF / 128, TOK / 128), 256>>>(
            x, W1 + (size_t)l * HD * DFF, b1 + (size_t)l * DFF, ff, TOK, DFF, HD);
        gemm_bias<0><<<dim3(HD / 128, TOK / 128), 256>>>(
            ff, W2 + (size_t)l * DFF * HD, b2 + (size_t)l * HD, y, TOK, HD, DFF);
        ln_res_kernel<<<TOK, 256>>>(x, y, l2s + (size_t)l * HD, l2b + (size_t)l * HD, x);
    }

    cls_kernel<<<(TOK * NLB + 255) / 256, 256>>>(x, Wcls, bcls, lg);
    crf_kernel<<<NB, 128>>>(lg, lab, am, cst, cen, ctr, llh, out);
    loss_kernel<<<1, 32>>>(llh, out);
}

// round 4
// speedup vs baseline: 1.2983x; 1.2983x over previous
#include <cuda_runtime.h>
#include <math.h>
#include <stdint.h>

// ---------------- problem constants ----------------
#define NB   16
#define NT   512
#define TOK  (NB*NT)        // 8192 tokens
#define HD   768
#define T3   (3*HD)         // 2304
#define DFF  3072
#define NHH  12
#define DH   64
#define NLB  9
#define NBH  (NB*NHH)       // 192
#define NLAY 4

// ---------------- scratch (static device globals; no runtime alloc) ----------------
__device__ float g_x[TOK*HD];
__device__ float g_qkv[TOK*T3];
__device__ float g_scores[(size_t)NBH*NT*NT];   // 201 MB
__device__ float g_ctx[TOK*HD];
__device__ float g_y[TOK*HD];
__device__ float g_ff[TOK*DFF];
__device__ float g_logits[TOK*NLB];
__device__ float g_llh[NB];

// ---------------- tf32 helpers ----------------
__device__ __forceinline__ void split_tf32(float x, uint32_t& hi, uint32_t& lo) {
    uint32_t h;
    asm("cvt.rna.tf32.f32 %0, %1;" : "=r"(h) : "f"(x));
    float hf = __uint_as_float(h);
    float r = x - hf;
    uint32_t l;
    asm("cvt.rna.tf32.f32 %0, %1;" : "=r"(l) : "f"(r));
    hi = h; lo = l;
}

__device__ __forceinline__ void mma_tf32(float* c, const uint32_t* a, const uint32_t* b) {
    asm volatile(
        "mma.sync.aligned.m16n8k8.row.col.f32.tf32.tf32.f32 "
        "{%0,%1,%2,%3}, {%4,%5,%6,%7}, {%8,%9}, {%0,%1,%2,%3};"
        : "+f"(c[0]), "+f"(c[1]), "+f"(c[2]), "+f"(c[3])
        : "r"(a[0]), "r"(a[1]), "r"(a[2]), "r"(a[3]), "r"(b[0]), "r"(b[1]));
}

__device__ __forceinline__ float gelu_tanh(float v) {
    float u = 0.7978845608028654f * (v + 0.044715f * v * v * v);
    return 0.5f * v * (1.f + tanhf(u));
}

// ---------------- reductions ----------------
__device__ __forceinline__ void reduce2_256(float& a, float& b) {
    __shared__ float sa[8], sb[8];
    #pragma unroll
    for (int o = 16; o; o >>= 1) {
        a += __shfl_xor_sync(0xffffffffu, a, o);
        b += __shfl_xor_sync(0xffffffffu, b, o);
    }
    int w = threadIdx.x >> 5;
    if ((threadIdx.x & 31) == 0) { sa[w] = a; sb[w] = b; }
    __syncthreads();
    a = 0.f; b = 0.f;
    #pragma unroll
    for (int i = 0; i < 8; i++) { a += sa[i]; b += sb[i]; }
}

// ---------------- embedding + LN ----------------
__global__ void __launch_bounds__(256) embed_ln_kernel(
    const int* __restrict__ ids, const int* __restrict__ tt,
    const float* __restrict__ we, const float* __restrict__ pe, const float* __restrict__ te,
    const float* __restrict__ sc, const float* __restrict__ bi, float* __restrict__ x)
{
    int tok = blockIdx.x;
    int t   = tok & (NT - 1);
    int tid = threadIdx.x;
    const float* w  = we + (size_t)ids[tok] * HD;
    const float* p  = pe + (size_t)t * HD;
    const float* ty = te + (size_t)tt[tok] * HD;
    float e[3]; float sum = 0.f, sq = 0.f;
    #pragma unroll
    for (int i = 0; i < 3; i++) {
        int c = tid + i * 256;
        float v = w[c] + p[c] + ty[c];
        e[i] = v; sum += v; sq += v * v;
    }
    reduce2_256(sum, sq);
    float mean = sum * (1.f / HD);
    float var  = sq * (1.f / HD) - mean * mean;
    float inv  = rsqrtf(var + 1e-12f);
    #pragma unroll
    for (int i = 0; i < 3; i++) {
        int c = tid + i * 256;
        x[(size_t)tok * HD + c] = (e[i] - mean) * inv * sc[c] + bi[c];
    }
}

// ---------------- residual + LN ----------------
__global__ void __launch_bounds__(256) ln_res_kernel(
    const float* __restrict__ xin, const float* __restrict__ y,
    const float* __restrict__ sc, const float* __restrict__ bi, float* __restrict__ xout)
{
    int tok = blockIdx.x;
    int tid = threadIdx.x;
    float e[3]; float sum = 0.f, sq = 0.f;
    #pragma unroll
    for (int i = 0; i < 3; i++) {
        int c = tid + i * 256;
        float v = xin[(size_t)tok * HD + c] + y[(size_t)tok * HD + c];
        e[i] = v; sum += v; sq += v * v;
    }
    reduce2_256(sum, sq);
    float mean = sum * (1.f / HD);
    float var  = sq * (1.f / HD) - mean * mean;
    float inv  = rsqrtf(var + 1e-12f);
    #pragma unroll
    for (int i = 0; i < 3; i++) {
        int c = tid + i * 256;
        xout[(size_t)tok * HD + c] = (e[i] - mean) * inv * sc[c] + bi[c];
    }
}

// ================= 3xTF32 GEMM: C[M,N] = A[M,K] @ B[K,N] (+bias / gelu) =================
// Tile 128x128x16, 256 threads (8 warps as 2x4), warp tile 64x32.
// EPI: 0 = +bias, 1 = +bias + gelu
template<int EPI>
__global__ void __launch_bounds__(256) gemm_tf32(
    const float* __restrict__ A, const float* __restrict__ B,
    const float* __restrict__ bias, float* __restrict__ C,
    int M, int N, int K)
{
    __shared__ float As[16][136];   // [k][m], stride 136 (mod 32 == 8) -> conflict-free frags
    __shared__ float Bs[16][136];   // [k][n]

    const int tid  = threadIdx.x;
    const int m0   = blockIdx.y * 128;
    const int n0   = blockIdx.x * 128;
    const int lane = tid & 31, warp = tid >> 5;
    const int wm = (warp >> 2) * 64;
    const int wn = (warp & 3) * 32;
    const int g  = lane >> 2, tg = lane & 3;

    const int arow = tid >> 1, acol = (tid & 1) * 8;
    const int brow = tid >> 4, bcol = (tid & 15) * 8;
    const float* Ap = A + (size_t)(m0 + arow) * K + acol;
    const float* Bp = B + (size_t)brow * N + n0 + bcol;

    float4 ra0 = *(const float4*)(Ap);
    float4 ra1 = *(const float4*)(Ap + 4);
    float4 rb0 = *(const float4*)(Bp);
    float4 rb1 = *(const float4*)(Bp + 4);

    float acc[16][4];
    #pragma unroll
    for (int i = 0; i < 16; i++) { acc[i][0] = acc[i][1] = acc[i][2] = acc[i][3] = 0.f; }

    const int TT = K >> 4;
    for (int t = 0; t < TT; t++) {
        As[acol + 0][arow] = ra0.x; As[acol + 1][arow] = ra0.y;
        As[acol + 2][arow] = ra0.z; As[acol + 3][arow] = ra0.w;
        As[acol + 4][arow] = ra1.x; As[acol + 5][arow] = ra1.y;
        As[acol + 6][arow] = ra1.z; As[acol + 7][arow] = ra1.w;
        *(float4*)&Bs[brow][bcol]     = rb0;
        *(float4*)&Bs[brow][bcol + 4] = rb1;
        __syncthreads();

        if (t + 1 < TT) {
            int ko = (t + 1) * 16;
            ra0 = *(const float4*)(Ap + ko);
            ra1 = *(const float4*)(Ap + ko + 4);
            rb0 = *(const float4*)(Bp + (size_t)ko * N);
            rb1 = *(const float4*)(Bp + (size_t)ko * N + 4);
        }

        #pragma unroll
        for (int kk = 0; kk < 16; kk += 8) {
            uint32_t ahi[16], alo[16], bhi[8], blo[8];
            #pragma unroll
            for (int mf = 0; mf < 4; mf++) {
                int mb = wm + mf * 16 + g;
                split_tf32(As[kk + tg][mb],         ahi[mf*4+0], alo[mf*4+0]);
                split_tf32(As[kk + tg][mb + 8],     ahi[mf*4+1], alo[mf*4+1]);
                split_tf32(As[kk + tg + 4][mb],     ahi[mf*4+2], alo[mf*4+2]);
                split_tf32(As[kk + tg + 4][mb + 8], ahi[mf*4+3], alo[mf*4+3]);
            }
            #pragma unroll
            for (int nf = 0; nf < 4; nf++) {
                int nb = wn + nf * 8 + g;
                split_tf32(Bs[kk + tg][nb],     bhi[nf*2+0], blo[nf*2+0]);
                split_tf32(Bs[kk + tg + 4][nb], bhi[nf*2+1], blo[nf*2+1]);
            }
            #pragma unroll
            for (int mf = 0; mf < 4; mf++)
                #pragma unroll
                for (int nf = 0; nf < 4; nf++) {
                    float* c = acc[mf * 4 + nf];
                    mma_tf32(c, &alo[mf*4], &bhi[nf*2]);
                    mma_tf32(c, &ahi[mf*4], &blo[nf*2]);
                    mma_tf32(c, &ahi[mf*4], &bhi[nf*2]);
                }
        }
        __syncthreads();
    }

    #pragma unroll
    for (int mf = 0; mf < 4; mf++) {
        #pragma unroll
        for (int nf = 0; nf < 4; nf++) {
            const float* c = acc[mf * 4 + nf];
            int mrow = m0 + wm + mf * 16 + g;
            int ncol = n0 + wn + nf * 8 + tg * 2;
            float b0 = bias[ncol], b1 = bias[ncol + 1];
            float v0 = c[0] + b0, v1 = c[1] + b1, v2 = c[2] + b0, v3 = c[3] + b1;
            if (EPI == 1) { v0 = gelu_tanh(v0); v1 = gelu_tanh(v1); v2 = gelu_tanh(v2); v3 = gelu_tanh(v3); }
            C[(size_t)mrow * N + ncol]           = v0;
            C[(size_t)mrow * N + ncol + 1]       = v1;
            C[(size_t)(mrow + 8) * N + ncol]     = v2;
            C[(size_t)(mrow + 8) * N + ncol + 1] = v3;
        }
    }
}

// ================= 3xTF32 QK^T: S[bh][512][512] = Q @ K^T =================
// Tile 128x128x16; A rows stride T3; B transposed-load (k contiguous in gmem).
__global__ void __launch_bounds__(256) qk_tf32(
    const float* __restrict__ qkv, float* __restrict__ scores)
{
    __shared__ float As[16][136];
    __shared__ float Bs[16][136];

    const int tid  = threadIdx.x;
    const int bh   = blockIdx.z;
    const int b    = bh / NHH, h = bh % NHH;
    const int m0   = blockIdx.y * 128;
    const int n0   = blockIdx.x * 128;
    const int lane = tid & 31, warp = tid >> 5;
    const int wm = (warp >> 2) * 64;
    const int wn = (warp & 3) * 32;
    const int g  = lane >> 2, tg = lane & 3;

    const int arow = tid >> 1, acol = (tid & 1) * 8;   // A: 128 rows x 16 k
    const int bnr  = tid >> 1, bkc  = (tid & 1) * 8;   // B: 128 n-cols x 16 k (transposed load)
    const float* Ap = qkv + (size_t)(b * NT + m0 + arow) * T3 + h * DH + acol;
    const float* Bp = qkv + (size_t)(b * NT + n0 + bnr) * T3 + HD + h * DH + bkc;

    float4 ra0 = *(const float4*)(Ap);
    float4 ra1 = *(const float4*)(Ap + 4);
    float4 rb0 = *(const float4*)(Bp);
    float4 rb1 = *(const float4*)(Bp + 4);

    float acc[16][4];
    #pragma unroll
    for (int i = 0; i < 16; i++) { acc[i][0] = acc[i][1] = acc[i][2] = acc[i][3] = 0.f; }

    const int TT = DH >> 4;   // 4
    for (int t = 0; t < TT; t++) {
        As[acol + 0][arow] = ra0.x; As[acol + 1][arow] = ra0.y;
        As[acol + 2][arow] = ra0.z; As[acol + 3][arow] = ra0.w;
        As[acol + 4][arow] = ra1.x; As[acol + 5][arow] = ra1.y;
        As[acol + 6][arow] = ra1.z; As[acol + 7][arow] = ra1.w;
        Bs[bkc + 0][bnr] = rb0.x; Bs[bkc + 1][bnr] = rb0.y;
        Bs[bkc + 2][bnr] = rb0.z; Bs[bkc + 3][bnr] = rb0.w;
        Bs[bkc + 4][bnr] = rb1.x; Bs[bkc + 5][bnr] = rb1.y;
        Bs[bkc + 6][bnr] = rb1.z; Bs[bkc + 7][bnr] = rb1.w;
        __syncthreads();

        if (t + 1 < TT) {
            int ko = (t + 1) * 16;
            ra0 = *(const float4*)(Ap + ko);
            ra1 = *(const float4*)(Ap + ko + 4);
            rb0 = *(const float4*)(Bp + ko);
            rb1 = *(const float4*)(Bp + ko + 4);
        }

        #pragma unroll
        for (int kk = 0; kk < 16; kk += 8) {
            uint32_t ahi[16], alo[16], bhi[8], blo[8];
            #pragma unroll
            for (int mf = 0; mf < 4; mf++) {
                int mb = wm + mf * 16 + g;
                split_tf32(As[kk + tg][mb],         ahi[mf*4+0], alo[mf*4+0]);
                split_tf32(As[kk + tg][mb + 8],     ahi[mf*4+1], alo[mf*4+1]);
                split_tf32(As[kk + tg + 4][mb],     ahi[mf*4+2], alo[mf*4+2]);
                split_tf32(As[kk + tg + 4][mb + 8], ahi[mf*4+3], alo[mf*4+3]);
            }
            #pragma unroll
            for (int nf = 0; nf < 4; nf++) {
                int nb = wn + nf * 8 + g;
                split_tf32(Bs[kk + tg][nb],     bhi[nf*2+0], blo[nf*2+0]);
                split_tf32(Bs[kk + tg + 4][nb], bhi[nf*2+1], blo[nf*2+1]);
            }
            #pragma unroll
            for (int mf = 0; mf < 4; mf++)
                #pragma unroll
                for (int nf = 0; nf < 4; nf++) {
                    float* c = acc[mf * 4 + nf];
                    mma_tf32(c, &alo[mf*4], &bhi[nf*2]);
                    mma_tf32(c, &ahi[mf*4], &blo[nf*2]);
                    mma_tf32(c, &ahi[mf*4], &bhi[nf*2]);
                }
        }
        __syncthreads();
    }

    float* out = scores + (size_t)bh * NT * NT;
    #pragma unroll
    for (int mf = 0; mf < 4; mf++)
        #pragma unroll
        for (int nf = 0; nf < 4; nf++) {
            const float* c = acc[mf * 4 + nf];
            int mrow = m0 + wm + mf * 16 + g;
            int ncol = n0 + wn + nf * 8 + tg * 2;
            out[(size_t)mrow * NT + ncol]           = c[0];
            out[(size_t)mrow * NT + ncol + 1]       = c[1];
            out[(size_t)(mrow + 8) * NT + ncol]     = c[2];
            out[(size_t)(mrow + 8) * NT + ncol + 1] = c[3];
        }
}

// ================= 3xTF32 S@V: ctx[b,m,h*64+n] = S @ V =================
// Tile 128x64x16, 8 warps as 2x4, warp tile 64x16 (mf=4, nf=2).
__global__ void __launch_bounds__(256) av_tf32(
    const float* __restrict__ scores, const float* __restrict__ qkv, float* __restrict__ ctx)
{
    __shared__ float As[16][136];   // S tile [k][m]
    __shared__ float Bs[16][72];    // V tile [k][n], stride 72 (mod 32 == 8)

    const int tid  = threadIdx.x;
    const int bh   = blockIdx.y;
    const int b    = bh / NHH, h = bh % NHH;
    const int m0   = blockIdx.x * 128;
    const int lane = tid & 31, warp = tid >> 5;
    const int wm = (warp >> 2) * 64;
    const int wn = (warp & 3) * 16;
    const int g  = lane >> 2, tg = lane & 3;

    const int arow = tid >> 1, acol = (tid & 1) * 8;   // S: 128 rows x 16 k
    const int brow = tid >> 4, bcol = (tid & 15) * 4;  // V: 16 k-rows x 64 n
    const float* Ap = scores + (size_t)bh * NT * NT + (size_t)(m0 + arow) * NT + acol;
    const float* Bp = qkv + (size_t)(b * NT + brow) * T3 + 2 * HD + h * DH + bcol;

    float4 ra0 = *(const float4*)(Ap);
    float4 ra1 = *(const float4*)(Ap + 4);
    float4 rb0 = *(const float4*)(Bp);

    float acc[8][4];
    #pragma unroll
    for (int i = 0; i < 8; i++) { acc[i][0] = acc[i][1] = acc[i][2] = acc[i][3] = 0.f; }

    const int TT = NT >> 4;   // 32
    for (int t = 0; t < TT; t++) {
        As[acol + 0][arow] = ra0.x; As[acol + 1][arow] = ra0.y;
        As[acol + 2][arow] = ra0.z; As[acol + 3][arow] = ra0.w;
        As[acol + 4][arow] = ra1.x; As[acol + 5][arow] = ra1.y;
        As[acol + 6][arow] = ra1.z; As[acol + 7][arow] = ra1.w;
        *(float4*)&Bs[brow][bcol] = rb0;
        __syncthreads();

        if (t + 1 < TT) {
            int ko = (t + 1) * 16;
            ra0 = *(const float4*)(Ap + ko);
            ra1 = *(const float4*)(Ap + ko + 4);
            rb0 = *(const float4*)(Bp + (size_t)ko * T3);
        }

        #pragma unroll
        for (int kk = 0; kk < 16; kk += 8) {
            uint32_t ahi[16], alo[16], bhi[4], blo[4];
            #pragma unroll
            for (int mf = 0; mf < 4; mf++) {
                int mb = wm + mf * 16 + g;
                split_tf32(As[kk + tg][mb],         ahi[mf*4+0], alo[mf*4+0]);
                split_tf32(As[kk + tg][mb + 8],     ahi[mf*4+1], alo[mf*4+1]);
                split_tf32(As[kk + tg + 4][mb],     ahi[mf*4+2], alo[mf*4+2]);
                split_tf32(As[kk + tg + 4][mb + 8], ahi[mf*4+3], alo[mf*4+3]);
            }
            #pragma unroll
            for (int nf = 0; nf < 2; nf++) {
                int nb = wn + nf * 8 + g;
                split_tf32(Bs[kk + tg][nb],     bhi[nf*2+0], blo[nf*2+0]);
                split_tf32(Bs[kk + tg + 4][nb], bhi[nf*2+1], blo[nf*2+1]);
            }
            #pragma unroll
            for (int mf = 0; mf < 4; mf++)
                #pragma unroll
                for (int nf = 0; nf < 2; nf++) {
                    float* c = acc[mf * 2 + nf];
                    mma_tf32(c, &alo[mf*4], &bhi[nf*2]);
                    mma_tf32(c, &ahi[mf*4], &blo[nf*2]);
                    mma_tf32(c, &ahi[mf*4], &bhi[nf*2]);
                }
        }
        __syncthreads();
    }

    #pragma unroll
    for (int mf = 0; mf < 4; mf++)
        #pragma unroll
        for (int nf = 0; nf < 2; nf++) {
            const float* c = acc[mf * 2 + nf];
            int mrow = m0 + wm + mf * 16 + g;
            int ncol = h * DH + wn + nf * 8 + tg * 2;
            float* o = ctx + (size_t)(b * NT + mrow) * HD + ncol;
            o[0] = c[0]; o[1] = c[1];
            o[(size_t)8 * HD] = c[2]; o[(size_t)8 * HD + 1] = c[3];
        }
}

// ---------------- softmax over key dim, with additive mask, scale=1/8 ----------------
__global__ void __launch_bounds__(128) softmax_kernel(
    float* __restrict__ scores, const int* __restrict__ amask)
{
    __shared__ float sm[4];
    int row = blockIdx.x;
    int bh  = row >> 9;
    int b   = bh / NHH;
    float* p = scores + (size_t)row * NT;
    int tid = threadIdx.x;
    float v[4]; float mx = -1e30f;
    #pragma unroll
    for (int c = 0; c < 4; c++) {
        int col = tid + c * 128;
        float madd = (1.f - (float)amask[b * NT + col]) * -1e9f;
        v[c] = p[col] * 0.125f + madd;
        mx = fmaxf(mx, v[c]);
    }
    #pragma unroll
    for (int o = 16; o; o >>= 1) mx = fmaxf(mx, __shfl_xor_sync(0xffffffffu, mx, o));
    if ((tid & 31) == 0) sm[tid >> 5] = mx;
    __syncthreads();
    mx = fmaxf(fmaxf(sm[0], sm[1]), fmaxf(sm[2], sm[3]));
    __syncthreads();
    float sum = 0.f;
    #pragma unroll
    for (int c = 0; c < 4; c++) { v[c] = __expf(v[c] - mx); sum += v[c]; }
    #pragma unroll
    for (int o = 16; o; o >>= 1) sum += __shfl_xor_sync(0xffffffffu, sum, o);
    if ((tid & 31) == 0) sm[tid >> 5] = sum;
    __syncthreads();
    sum = sm[0] + sm[1] + sm[2] + sm[3];
    float inv = 1.f / sum;
    #pragma unroll
    for (int c = 0; c < 4; c++) p[tid + c * 128] = v[c] * inv;
}

// ---------------- classifier ----------------
__global__ void __launch_bounds__(256) cls_kernel(
    const float* __restrict__ x, const float* __restrict__ W,
    const float* __restrict__ bias, float* __restrict__ out)
{
    int idx = blockIdx.x * blockDim.x + threadIdx.x;
    if (idx >= TOK * NLB) return;
    int tok = idx / NLB, n = idx % NLB;
    const float* xr = x + (size_t)tok * HD;
    float s = bias[n];
    #pragma unroll 8
    for (int k = 0; k < HD; k++) s = fmaf(xr[k], W[k * NLB + n], s);
    out[idx] = s;
}

// ---------------- CRF ----------------
__global__ void __launch_bounds__(128) crf_kernel(
    const float* __restrict__ logits, const int* __restrict__ labels,
    const int* __restrict__ amask, const float* __restrict__ startv,
    const float* __restrict__ endv, const float* __restrict__ trans,
    float* __restrict__ llh, float* __restrict__ dout)
{
    __shared__ float em[511 * NLB];
    __shared__ float tr[NLB * NLB];
    __shared__ unsigned char bp[510 * NLB];
    __shared__ float mk[511];
    __shared__ int   tg[511];
    __shared__ float sd[NLB], sv[NLB];

    int b = blockIdx.x, tid = threadIdx.x;
    const float* lp = logits + (size_t)(b * NT + 1) * NLB;
    for (int i = tid; i < 511 * NLB; i += blockDim.x) em[i] = lp[i];
    for (int i = tid; i < NLB * NLB; i += blockDim.x) tr[i] = trans[i];
    for (int i = tid; i < 511; i += blockDim.x) {
        mk[i] = (float)amask[b * NT + 1 + i];
        tg[i] = labels[b * NT + 1 + i];
    }
    __syncthreads();

    if (tid < 32) {
        int j = tid;
        float tc[NLB];
        if (j < NLB) {
            #pragma unroll
            for (int i = 0; i < NLB; i++) tc[i] = tr[i * NLB + j];
            sd[j] = startv[j] + em[j];
            sv[j] = sd[j];
        }
        __syncwarp();
        float num = 0.f; int prev = 0;
        if (j == 0) { prev = tg[0]; num = startv[prev] + em[prev]; }

        for (int s = 1; s < 511; s++) {
            float m = mk[s];
            float nd = 0.f, nv = 0.f; int bi = 0;
            if (j < NLB) {
                float e = em[s * NLB + j];
                float mx = -1e30f;
                #pragma unroll
                for (int i = 0; i < NLB; i++) { float v = sd[i] + tc[i]; mx = fmaxf(mx, v); }
                float sum = 0.f;
                #pragma unroll
                for (int i = 0; i < NLB; i++) sum += __expf(sd[i] + tc[i] - mx);
                nd = mx + __logf(sum) + e;
                float bv = -1e30f;
                #pragma unroll
                for (int i = 0; i < NLB; i++) {
                    float v = sv[i] + tc[i];
                    if (v > bv) { bv = v; bi = i; }
                }
                bp[(s - 1) * NLB + j] = (unsigned char)bi;
                nv = bv + e;
            }
            __syncwarp();
            if (j < NLB && m > 0.f) { sd[j] = nd; sv[j] = nv; }
            if (j == 0) {
                int t = tg[s];
                num += m * (tr[prev * NLB + t] + em[s * NLB + t]);
                if (m > 0.f) prev = t;
            }
            __syncwarp();
        }

        if (j == 0) {
            num += endv[prev];
            float mx = -1e30f;
            #pragma unroll
            for (int i = 0; i < NLB; i++) mx = fmaxf(mx, sd[i] + endv[i]);
            float sum = 0.f;
            #pragma unroll
            for (int i = 0; i < NLB; i++) sum += __expf(sd[i] + endv[i] - mx);
            float den = mx + __logf(sum);
            llh[b] = num - den;

            float bv = -1e30f; int last = 0;
            #pragma unroll
            for (int i = 0; i < NLB; i++) {
                float v = sv[i] + endv[i];
                if (v > bv) { bv = v; last = i; }
            }
            float* pd = dout + 1 + (size_t)b * 511;
            pd[510] = (float)last;
            for (int s = 509; s >= 0; s--) {
                last = bp[s * NLB + last];
                pd[s] = (float)last;
            }
        }
    }
}

__global__ void loss_kernel(const float* __restrict__ llh, float* __restrict__ dout)
{
    if (threadIdx.x == 0) {
        float s = 0.f;
        for (int i = 0; i < NB; i++) s += llh[i];
        dout[0] = -s / (float)NB;
    }
}

// ---------------- launcher ----------------
extern "C" void kernel_launch(void* const* d_in, const int* in_sizes, int n_in,
                              void* d_out, int out_size)
{
    (void)in_sizes; (void)n_in; (void)out_size;
    const int*   ids  = (const int*)d_in[0];
    const int*   am   = (const int*)d_in[1];
    const int*   tti  = (const int*)d_in[2];
    const int*   lab  = (const int*)d_in[3];
    const float* we   = (const float*)d_in[4];
    const float* pe   = (const float*)d_in[5];
    const float* te   = (const float*)d_in[6];
    const float* elns = (const float*)d_in[7];
    const float* elnb = (const float*)d_in[8];
    const float* Wqkv = (const float*)d_in[9];
    const float* bqkv = (const float*)d_in[10];
    const float* Wo   = (const float*)d_in[11];
    const float* bo   = (const float*)d_in[12];
    const float* l1s  = (const float*)d_in[13];
    const float* l1b  = (const float*)d_in[14];
    const float* W1   = (const float*)d_in[15];
    const float* b1   = (const float*)d_in[16];
    const float* W2   = (const float*)d_in[17];
    const float* b2   = (const float*)d_in[18];
    const float* l2s  = (const float*)d_in[19];
    const float* l2b  = (const float*)d_in[20];
    const float* Wcls = (const float*)d_in[21];
    const float* bcls = (const float*)d_in[22];
    const float* cst  = (const float*)d_in[23];
    const float* cen  = (const float*)d_in[24];
    const float* ctr  = (const float*)d_in[25];
    float* out = (float*)d_out;

    float *x, *qkv, *sc, *ctx, *y, *ff, *lg, *llh;
    cudaGetSymbolAddress((void**)&x,   g_x);
    cudaGetSymbolAddress((void**)&qkv, g_qkv);
    cudaGetSymbolAddress((void**)&sc,  g_scores);
    cudaGetSymbolAddress((void**)&ctx, g_ctx);
    cudaGetSymbolAddress((void**)&y,   g_y);
    cudaGetSymbolAddress((void**)&ff,  g_ff);
    cudaGetSymbolAddress((void**)&lg,  g_logits);
    cudaGetSymbolAddress((void**)&llh, g_llh);

    embed_ln_kernel<<<TOK, 256>>>(ids, tti, we, pe, te, elns, elnb, x);

    for (int l = 0; l < NLAY; l++) {
        gemm_tf32<0><<<dim3(T3 / 128, TOK / 128), 256>>>(
            x, Wqkv + (size_t)l * HD * T3, bqkv + (size_t)l * T3, qkv, TOK, T3, HD);
        qk_tf32<<<dim3(4, 4, NBH), 256>>>(qkv, sc);
        softmax_kernel<<<NBH * NT, 128>>>(sc, am);
        av_tf32<<<dim3(4, NBH), 256>>>(sc, qkv, ctx);
        gemm_tf32<0><<<dim3(HD / 128, TOK / 128), 256>>>(
            ctx, Wo + (size_t)l * HD * HD, bo + (size_t)l * HD, y, TOK, HD, HD);
        ln_res_kernel<<<TOK, 256>>>(x, y, l1s + (size_t)l * HD, l1b + (size_t)l * HD, x);
        gemm_tf32<1><<<dim3(DFF / 128, TOK / 128), 256>>>(
            x, W1 + (size_t)l * HD * DFF, b1 + (size_t)l * DFF, ff, TOK, DFF, HD);
        gemm_tf32<0><<<dim3(HD / 128, TOK / 128), 256>>>(
            ff, W2 + (size_t)l * DFF * HD, b2 + (size_t)l * HD, y, TOK, HD, DFF);
        ln_res_kernel<<<TOK, 256>>>(x, y, l2s + (size_t)l * HD, l2b + (size_t)l * HD, x);
    }

    cls_kernel<<<(TOK * NLB + 255) / 256, 256>>>(x, Wcls, bcls, lg);
    crf_kernel<<<NB, 128>>>(lg, lab, am, cst, cen, ctr, llh, out);
    loss_kernel<<<1, 32>>>(llh, out);
}